// round 17
// baseline (speedup 1.0000x reference)
#include <cuda_runtime.h>

#define NN 1024
#define EE 2048
#define HID 192
#define NL 4
#define NAUG 1152
#define MM (HID*HID)          // 36864
#define RAD 132               // dup-A row stride (words), 16B-aligned
#define SMEM_MAIN ((192*RAD + 2*192*64)*4)   // 199680 B

typedef unsigned long long ull;

// ---------------- device scratch (allocation-free) ----------------
__device__ float g_S[4*NN*4];
__device__ float g_h0[NN*HID];
__device__ float g_h1[NN*HID];
__device__ float g_Y[NN*NAUG];
__device__ float g_B[NL][HID*NAUG];   // [layer][k][n] fp32
__device__ unsigned g_bar;

// ---------------- helpers ----------------
__device__ __forceinline__ void fma2(ull &c, ull a, ull b) {
    asm("fma.rn.f32x2 %0, %1, %2, %0;" : "+l"(c) : "l"(a), "l"(b));
}
__device__ __forceinline__ float2 up2(ull a) {
    float2 f; asm("mov.b64 {%0, %1}, %2;" : "=f"(f.x), "=f"(f.y) : "l"(a)); return f;
}
__device__ __forceinline__ float4 ldcg4(const float4* p) { return __ldcg(p); }
__device__ __forceinline__ void gbar(unsigned target) {
    __threadfence();
    __syncthreads();
    if (threadIdx.x == 0) {
        atomicAdd(&g_bar, 1u);
        while (*((volatile unsigned*)&g_bar) < target) __nanosleep(32);
    }
    __syncthreads();
}

// ---------------- single persistent kernel ----------------
__global__ void __launch_bounds__(512, 1)
k_all(const float* __restrict__ x, const int* __restrict__ ei,
      const float* __restrict__ attr,
      const float* __restrict__ cw, const float* __restrict__ cbb,
      const float* __restrict__ conv_b,
      const float* __restrict__ lng, const float* __restrict__ lnb,
      const float* __restrict__ ow, const float* __restrict__ ob,
      const float* __restrict__ eenc_w, const float* __restrict__ eenc_b,
      const float* __restrict__ nn1_w,  const float* __restrict__ nn1_b,
      const float* __restrict__ nn2_w,  const float* __restrict__ nn2_b,
      const float* __restrict__ root_w,
      float* __restrict__ out) {
    extern __shared__ float sm[];
    float* sA  = sm;                 // [192][RAD] dup (z,z) pairs
    float* sB0 = sm + 192*RAD;       // [192][64]
    float* sB1 = sB0 + 192*64;
    __shared__ float2 sG[5*HID];
    int t = threadIdx.x, b = blockIdx.x;
    int m0  = (b & 15) * 64;
    int njA = b >> 4;                // 0..8 ; partner n-tile njA+9

    // ================= phase 0: cheb prep (block 0) + Mstack (all blocks) =================
    if (b == 0) {
        float* sdeg = sm;                 // [1024]
        float* sS   = sm + 1024;          // [4][1024][4]
        float* sX   = sm + 1024 + 16384;  // [1024][4]
        #pragma unroll
        for (int i = 0; i < 2; i++) sdeg[t + 512*i] = 0.f;
        #pragma unroll
        for (int i = 0; i < 32; i++) sS[t + 512*i] = 0.f;
        #pragma unroll
        for (int i = 0; i < 8; i++) sX[t + 512*i] = x[t + 512*i];
        __syncthreads();
        int s[4], d[4]; float w[4];
        #pragma unroll
        for (int j = 0; j < 4; j++) {
            int e = t*4 + j;
            s[j] = ei[e]; d[j] = ei[EE + e];
            atomicAdd(&sdeg[s[j]], 1.f);
        }
        __syncthreads();
        float dv[2];
        #pragma unroll
        for (int i = 0; i < 2; i++) dv[i] = sdeg[t + 512*i];
        __syncthreads();
        #pragma unroll
        for (int i = 0; i < 2; i++) sdeg[t + 512*i] = dv[i] > 0.f ? rsqrtf(dv[i]) : 0.f;
        __syncthreads();
        #pragma unroll
        for (int j = 0; j < 4; j++) w[j] = -sdeg[s[j]] * sdeg[d[j]];
        #pragma unroll
        for (int j = 0; j < 4; j++)
            #pragma unroll
            for (int c = 0; c < 4; c++)
                atomicAdd(&sS[d[j]*4 + c], w[j] * sX[s[j]*4 + c]);
        __syncthreads();
        #pragma unroll
        for (int j = 0; j < 4; j++)
            #pragma unroll
            for (int c = 0; c < 4; c++)
                atomicAdd(&sS[4096 + d[j]*4 + c], w[j] * sS[s[j]*4 + c]);
        __syncthreads();
        #pragma unroll
        for (int j = 0; j < 4; j++)
            #pragma unroll
            for (int c = 0; c < 4; c++)
                atomicAdd(&sS[8192 + d[j]*4 + c],
                          w[j] * (2.f*sS[4096 + s[j]*4 + c] - sX[s[j]*4 + c]));
        __syncthreads();
        #pragma unroll
        for (int j = 0; j < 4; j++)
            #pragma unroll
            for (int c = 0; c < 4; c++)
                atomicAdd(&sS[12288 + d[j]*4 + c],
                          w[j] * (2.f*sS[8192 + s[j]*4 + c] - sS[s[j]*4 + c]));
        __syncthreads();
        #pragma unroll
        for (int i = 0; i < 32; i++) g_S[t + 512*i] = sS[t + 512*i];
        __syncthreads();
    }
    // ---- Mstack: layer = b&3, slice = b>>2; 2 threads per m4, pipelined loads ----
    {
        int layer = b & 3, slice = b >> 2;
        if (t < HID) {
            float acc5[5] = {0.f, 0.f, 0.f, 0.f, 0.f};
            const float* W1 = nn1_w + layer*MM;
            for (int jb = 0; jb < HID; jb += 8) {
                float wv[8];
                #pragma unroll
                for (int u = 0; u < 8; u++) wv[u] = __ldg(W1 + (jb + u)*HID + t);
                #pragma unroll
                for (int u = 0; u < 8; u++) {
                    int j0 = jb + u;
                    acc5[0] += eenc_w[j0]*wv[u];
                    acc5[1] += eenc_w[HID + j0]*wv[u];
                    acc5[2] += eenc_w[2*HID + j0]*wv[u];
                    acc5[3] += eenc_w[3*HID + j0]*wv[u];
                    acc5[4] += eenc_b[j0]*wv[u];
                }
            }
            acc5[4] += nn1_b[layer*HID + t];
            #pragma unroll
            for (int k = 0; k < 5; k++) sG[k*HID + t] = make_float2(acc5[k], acc5[k]);
        }
        if (t < 256) {
            int m = slice*1024 + t*4;
            int j = m / HID, o = m - j*HID;
            float4 v = __ldg((const float4*)(root_w + (size_t)layer*MM + m));
            *(float4*)(g_B[layer] + j*NAUG + 5*HID + o) = v;
        }
        __syncthreads();

        int m4 = (slice*256 + (t >> 1)) * 4;
        int jh = t & 1;
        const float* Wj = nn2_w + (size_t)layer * HID * MM + (size_t)jh * 96 * MM + m4;
        ull acc[5][2] = {};
        ulonglong2 va[8], vb[8];
        #pragma unroll
        for (int u = 0; u < 8; u++) va[u] = *(const ulonglong2*)(Wj + (size_t)u*MM);
        for (int it = 0; it < 6; it++) {
            int j0 = it*16;
            #pragma unroll
            for (int u = 0; u < 8; u++)
                vb[u] = *(const ulonglong2*)(Wj + (size_t)(j0 + 8 + u)*MM);
            #pragma unroll
            for (int u = 0; u < 8; u++) {
                int j = jh*96 + j0 + u;
                #pragma unroll
                for (int k = 0; k < 5; k++) {
                    ull gk = *(const ull*)&sG[k*HID + j];
                    fma2(acc[k][0], gk, va[u].x);
                    fma2(acc[k][1], gk, va[u].y);
                }
            }
            if (it < 5) {
                #pragma unroll
                for (int u = 0; u < 8; u++)
                    va[u] = *(const ulonglong2*)(Wj + (size_t)(j0 + 16 + u)*MM);
            }
            #pragma unroll
            for (int u = 0; u < 8; u++) {
                int j = jh*96 + j0 + 8 + u;
                #pragma unroll
                for (int k = 0; k < 5; k++) {
                    ull gk = *(const ull*)&sG[k*HID + j];
                    fma2(acc[k][0], gk, vb[u].x);
                    fma2(acc[k][1], gk, vb[u].y);
                }
            }
        }
        float2 r[5][2];
        #pragma unroll
        for (int k = 0; k < 5; k++)
            #pragma unroll
            for (int h = 0; h < 2; h++) {
                ull other = __shfl_xor_sync(0xffffffffu, acc[k][h], 1);
                float2 a = up2(acc[k][h]), bo = up2(other);
                r[k][h] = make_float2(a.x + bo.x, a.y + bo.y);
            }
        if (jh == 0) {
            float4 bv = __ldg((const float4*)(nn2_b + (size_t)layer*MM + m4));
            r[4][0].x += bv.x; r[4][0].y += bv.y;
            r[4][1].x += bv.z; r[4][1].y += bv.w;
            int j2 = m4 / HID;
            int o  = m4 - j2 * HID;
            float* dst = g_B[layer] + j2*NAUG + o;
            #pragma unroll
            for (int k = 0; k < 5; k++) {
                *(float2*)(dst + k*HID)     = r[k][0];
                *(float2*)(dst + k*HID + 2) = r[k][1];
            }
        }
    }
    gbar(144u);

    // ================= phase 1: cheb -> sA directly (t<256) + B0 prefetch (t>=256) =================
    if (t < 256) {
        int m = t >> 2, q = t & 3, r = m0 + m;
        float xv[4], s1v[4], t2v[4], t3v[4], t4v[4];
        #pragma unroll
        for (int c = 0; c < 4; c++) {
            float X  = __ldg(x + r*4 + c);
            float S1 = g_S[r*4+c],        S2 = g_S[4096 + r*4+c];
            float S3 = g_S[8192 + r*4+c], S4 = g_S[12288 + r*4+c];
            xv[c] = X; s1v[c] = S1;
            t2v[c] = 2.f*S2 - X;
            t3v[c] = 2.f*S3 - S1;
            t4v[c] = 2.f*S4 - 2.f*S2 + X;
        }
        for (int i = 0; i < 12; i++) {
            #pragma unroll
            for (int e = 0; e < 4; e++) {
                int o = q*48 + i*4 + e;
                float z = __ldg(cbb + o);
                #pragma unroll
                for (int c = 0; c < 4; c++)
                    z += xv[c] *__ldg(cw + c*HID + o)
                       + s1v[c]*__ldg(cw + (4+c)*HID + o)
                       + t2v[c]*__ldg(cw + (8+c)*HID + o)
                       + t3v[c]*__ldg(cw + (12+c)*HID + o)
                       + t4v[c]*__ldg(cw + (16+c)*HID + o);
                *(float2*)(sA + o*RAD + 2*m) = make_float2(z, z);
            }
        }
    } else {
        int li = t - 256;
        const float* Bm = g_B[0];
        #pragma unroll 4
        for (int i = 0; i < 24; i++) {
            int f = li + 256*i;
            int tile = f / 3072, rr = f - tile*3072;
            int kk = rr >> 4, w4 = rr & 15;
            int nj = tile ? (njA + 9) : njA;
            float4 v = __ldcg((const float4*)(Bm + kk*NAUG + nj*64 + w4*4));
            *(float4*)((tile ? sB1 : sB0) + kk*64 + w4*4) = v;
        }
    }
    __syncthreads();

    // ================= layers =================
    for (int L = 0; L < NL; L++) {
        const float* hin  = (L & 1) ? g_h1 : g_h0;
        float*       hout = (L & 1) ? g_h0 : g_h1;
        int do_ln = (L > 0);

        if (L > 0) {
            // A prologue: 64 rows x 4 threads/row, LN in registers, dup store
            if (t < 256) {
                int m = t >> 2, q = t & 3;
                const float4* rp = (const float4*)(hin + (size_t)(m0 + m)*HID) + q*12;
                float4 v[12];
                #pragma unroll
                for (int i = 0; i < 12; i++) v[i] = ldcg4(rp + i);
                float s = 0.f, qq = 0.f;
                #pragma unroll
                for (int i = 0; i < 12; i++) {
                    s  += (v[i].x + v[i].y) + (v[i].z + v[i].w);
                    qq += v[i].x*v[i].x + v[i].y*v[i].y + v[i].z*v[i].z + v[i].w*v[i].w;
                }
                s  += __shfl_xor_sync(0xffffffffu, s, 1);
                s  += __shfl_xor_sync(0xffffffffu, s, 2);
                qq += __shfl_xor_sync(0xffffffffu, qq, 1);
                qq += __shfl_xor_sync(0xffffffffu, qq, 2);
                float mu = s * (1.f/192.f);
                float rs = rsqrtf(qq*(1.f/192.f) - mu*mu + 1e-5f);
                #pragma unroll
                for (int i = 0; i < 12; i++) {
                    int k = q*48 + i*4;
                    float vv[4] = {v[i].x, v[i].y, v[i].z, v[i].w};
                    #pragma unroll
                    for (int e = 0; e < 4; e++) {
                        float z = fmaxf(0.f, (vv[e] - mu)*rs*__ldg(lng + L*HID + k + e)
                                             + __ldg(lnb + L*HID + k + e));
                        *(float2*)(sA + (k + e)*RAD + 2*m) = make_float2(z, z);
                    }
                }
            }
            __syncthreads();
        }

        // ---- GEMM main: dup-A broadcast, 13 instr/kk ----
        {
            int half = t >> 8, th = t & 255;
            int w = th >> 5, lane = th & 31;
            const float* sB = half ? sB1 : sB0;
            int nj = half ? (njA + 9) : njA;
            const float* aBase = sA + 16*w;
            const float* bBase = sB + 2*lane;
            ull acc[8] = {};
            #pragma unroll 4
            for (int kk = 0; kk < 192; kk++) {
                ulonglong2 aA = *(const ulonglong2*)(aBase + kk*RAD);
                ulonglong2 aB = *(const ulonglong2*)(aBase + kk*RAD + 4);
                ulonglong2 aC = *(const ulonglong2*)(aBase + kk*RAD + 8);
                ulonglong2 aD = *(const ulonglong2*)(aBase + kk*RAD + 12);
                ull bp = *(const ull*)(bBase + kk*64);
                fma2(acc[0], aA.x, bp); fma2(acc[1], aA.y, bp);
                fma2(acc[2], aB.x, bp); fma2(acc[3], aB.y, bp);
                fma2(acc[4], aC.x, bp); fma2(acc[5], aC.y, bp);
                fma2(acc[6], aD.x, bp); fma2(acc[7], aD.y, bp);
            }
            int n0 = nj*64;
            int nc = 2*lane;
            if (nj < 15) {
                #pragma unroll
                for (int i = 0; i < 8; i++)
                    *(float2*)(g_Y + (size_t)(m0 + 8*w + i)*NAUG + n0 + nc) = up2(acc[i]);
            } else {
                int ob2 = n0 - 960 + nc;
                float2 cbv = *(const float2*)(conv_b + L*HID + ob2);
                #pragma unroll
                for (int i = 0; i < 8; i++) {
                    int row = m0 + 8*w + i;
                    float2 r = up2(acc[i]);
                    r.x += cbv.x; r.y += cbv.y;
                    if (do_ln) {
                        float2 hv = __ldcg((const float2*)(hin + (size_t)row*HID + ob2));
                        r.x += hv.x; r.y += hv.y;
                    }
                    *(float2*)(hout + (size_t)row*HID + ob2) = r;
                }
            }
        }
        gbar(144u*(2 + 2*L));

        // ---- escatter (t<384) + B-prefetch layer L+1 (t>=384) ----
        if (t < 384) {
            int g = t / 48, o4 = t - g*48;
            #pragma unroll
            for (int i = 0; i < 2; i++) {
                int e = b*8 + g + 1152*i;
                if (e < EE) {
                    int s = __ldg(ei + e), d = __ldg(ei + EE + e);
                    float4 a = __ldg((const float4*)(attr + e*4));
                    const float4* Ys = (const float4*)(g_Y + (size_t)s*NAUG);
                    float4 y0 = ldcg4(Ys + o4),       y1 = ldcg4(Ys + 48 + o4);
                    float4 y2 = ldcg4(Ys + 96 + o4),  y3 = ldcg4(Ys + 144 + o4);
                    float4 y4 = ldcg4(Ys + 192 + o4);
                    float4 v;
                    v.x = y4.x + a.x*y0.x + a.y*y1.x + a.z*y2.x + a.w*y3.x;
                    v.y = y4.y + a.x*y0.y + a.y*y1.y + a.z*y2.y + a.w*y3.y;
                    v.z = y4.z + a.x*y0.z + a.y*y1.z + a.z*y2.z + a.w*y3.z;
                    v.w = y4.w + a.x*y0.w + a.y*y1.w + a.z*y2.w + a.w*y3.w;
                    float* hp = hout + (size_t)d*HID + o4*4;
                    atomicAdd(hp+0, v.x); atomicAdd(hp+1, v.y);
                    atomicAdd(hp+2, v.z); atomicAdd(hp+3, v.w);
                }
            }
        } else if (L < NL - 1) {
            int li = t - 384;
            const float* Bm = g_B[L + 1];
            #pragma unroll 4
            for (int i = 0; i < 48; i++) {
                int f = li + 128*i;
                int tile = f / 3072, rr = f - tile*3072;
                int kk = rr >> 4, w4 = rr & 15;
                int nj = tile ? (njA + 9) : njA;
                float4 v = __ldcg((const float4*)(Bm + kk*NAUG + nj*64 + w4*4));
                *(float4*)((tile ? sB1 : sB0) + kk*64 + w4*4) = v;
            }
        }
        gbar(144u*(3 + 2*L));
    }

    // ================= final LN + head (warp per row; h final = g_h0) =================
    {
        int w = t >> 5, l = t & 31;
        if (w < 8) {
            int r = b + 144*w;
            if (r < NN) {
                float v[6];
                #pragma unroll
                for (int j = 0; j < 6; j++) v[j] = __ldcg(g_h0 + r*HID + l + 32*j);
                float s = ((v[0]+v[1])+(v[2]+v[3]))+(v[4]+v[5]);
                float q = v[0]*v[0]+v[1]*v[1]+v[2]*v[2]+v[3]*v[3]+v[4]*v[4]+v[5]*v[5];
                #pragma unroll
                for (int o = 16; o > 0; o >>= 1) {
                    s += __shfl_xor_sync(0xffffffffu, s, o);
                    q += __shfl_xor_sync(0xffffffffu, q, o);
                }
                float mu = s * (1.f/192.f);
                float rs = rsqrtf(q*(1.f/192.f) - mu*mu + 1e-5f);
                float p0 = 0.f, p1 = 0.f;
                #pragma unroll
                for (int j = 0; j < 6; j++) {
                    int c = l + 32*j;
                    float z = fmaxf(0.f, (v[j] - mu)*rs*__ldg(lng + c) + __ldg(lnb + c));
                    p0 += z * __ldg(ow + c*2);
                    p1 += z * __ldg(ow + c*2 + 1);
                }
                #pragma unroll
                for (int o = 16; o > 0; o >>= 1) {
                    p0 += __shfl_xor_sync(0xffffffffu, p0, o);
                    p1 += __shfl_xor_sync(0xffffffffu, p1, o);
                }
                if (l == 0) {
                    out[r*2]     = p0 + __ldg(ob);
                    out[r*2 + 1] = p1 + __ldg(ob + 1);
                }
            }
        }
    }

    // ---- safe barrier reset for graph replay ----
    __syncthreads();
    if (t == 0) {
        atomicAdd(&g_bar, 1u);
        if (b == 0) {
            while (*((volatile unsigned*)&g_bar) < 1440u) __nanosleep(32);
            atomicExch(&g_bar, 0u);
        }
    }
}

// ---------------- launcher ----------------
extern "C" void kernel_launch(void* const* d_in, const int* in_sizes, int n_in,
                              void* d_out, int out_size) {
    const float* x       = (const float*)d_in[0];
    const int*   ei      = (const int*)  d_in[1];
    const float* attr    = (const float*)d_in[2];
    const float* cheb_w  = (const float*)d_in[4];
    const float* cheb_b  = (const float*)d_in[5];
    const float* eenc_w  = (const float*)d_in[6];
    const float* eenc_b  = (const float*)d_in[7];
    const float* nn1_w   = (const float*)d_in[8];
    const float* nn1_b   = (const float*)d_in[9];
    const float* nn2_w   = (const float*)d_in[10];
    const float* nn2_b   = (const float*)d_in[11];
    const float* root_w  = (const float*)d_in[12];
    const float* conv_b  = (const float*)d_in[13];
    const float* ln_g    = (const float*)d_in[14];
    const float* ln_b    = (const float*)d_in[15];
    const float* out_w   = (const float*)d_in[16];
    const float* out_b   = (const float*)d_in[17];
    float* out = (float*)d_out;

    cudaFuncSetAttribute(k_all, cudaFuncAttributeMaxDynamicSharedMemorySize, SMEM_MAIN);

    k_all<<<144, 512, SMEM_MAIN>>>(x, ei, attr, cheb_w, cheb_b, conv_b,
                                   ln_g, ln_b, out_w, out_b,
                                   eenc_w, eenc_b, nn1_w, nn1_b, nn2_w, nn2_b,
                                   root_w, out);
}